// round 1
// baseline (speedup 1.0000x reference)
#include <cuda_runtime.h>
#include <cuda_bf16.h>

// ---------------------------------------------------------------------------
// BM25 scoring, restructured:
//   score = sum_v  hq[v] * (hq[v]/(K3+hq[v])) * (K1*hp[v]/(hp[v]+C1)) * idf(DF[v])
//   out   = sigmoid(score)
// Pass B: float histograms of both id rows via L2 atomics.
// Pass C: per-vocab scoring + re-zero histograms (restores invariant).
// Pass D: sigmoid + reset accumulator.
// ---------------------------------------------------------------------------

#define VOCAB_MAX (1 << 20)   // 1,048,576 >= 1,000,000

__device__ float g_hq[VOCAB_MAX];   // zero at module load; every launch restores zeros
__device__ float g_hp[VOCAB_MAX];
__device__ float g_acc;             // score accumulator; reset by finalize

// ---------------- Pass B: histogram ----------------
__global__ __launch_bounds__(256)
void bm25_hist(const int4* __restrict__ ids4, int n4, int half4, unsigned vocab) {
    int stride = gridDim.x * blockDim.x;
    for (int i = blockIdx.x * blockDim.x + threadIdx.x; i < n4; i += stride) {
        int4 t = ids4[i];
        float* tbl = (i < half4) ? g_hq : g_hp;   // int4 groups never straddle rows (L % 4 == 0)
        if ((unsigned)t.x < vocab) atomicAdd(tbl + t.x, 1.0f);
        if ((unsigned)t.y < vocab) atomicAdd(tbl + t.y, 1.0f);
        if ((unsigned)t.z < vocab) atomicAdd(tbl + t.z, 1.0f);
        if ((unsigned)t.w < vocab) atomicAdd(tbl + t.w, 1.0f);
    }
}

// ---------------- Pass C: per-vocab scoring ----------------
__device__ __forceinline__ float bm25_term(float cq, float cp, float d, float C1) {
    const float K1 = 1.2f;
    const float K3 = 8.0f;
    // idf = log2((N - d + 0.5)/(d + 0.5))
    //     = log2(N + 0.5) + log2(1 - d/(N+0.5)) - log2(d + 0.5)
    //    ~= LOG2_NP - d*CT - log2(d + 0.5)        (|d|/N <= 1.1e-3, err < 1e-6)
    const float LOG2_NP = 23.0759147f;            // log2(8841823.5)
    const float CT      = 1.631670e-7f;           // 1/((N+0.5)*ln2)
    float idf = (LOG2_NP - d * CT) - __log2f(d + 0.5f);
    // hq * (cq/(K3+cq)) * (K1*cp/(cp+C1)) merged into a single divide
    float num = cq * cq * (K1 * cp);
    float den = (K3 + cq) * (cp + C1);
    return __fdividef(num, den) * idf;            // exact 0 when cq==0 or cp==0
}

__global__ __launch_bounds__(256)
void bm25_score(const float4* __restrict__ df4, int n4, float C1) {
    float4* hq4 = reinterpret_cast<float4*>(g_hq);
    float4* hp4 = reinterpret_cast<float4*>(g_hp);
    const float4 z4 = make_float4(0.f, 0.f, 0.f, 0.f);

    float sum = 0.f;
    int stride = gridDim.x * blockDim.x;
    for (int i = blockIdx.x * blockDim.x + threadIdx.x; i < n4; i += stride) {
        float4 q = hq4[i];  hq4[i] = z4;          // read + restore zeros (L2-resident)
        float4 p = hp4[i];  hp4[i] = z4;
        float4 d = df4[i];
        sum += bm25_term(q.x, p.x, d.x, C1);
        sum += bm25_term(q.y, p.y, d.y, C1);
        sum += bm25_term(q.z, p.z, d.z, C1);
        sum += bm25_term(q.w, p.w, d.w, C1);
    }

    // warp reduce
    #pragma unroll
    for (int off = 16; off > 0; off >>= 1)
        sum += __shfl_down_sync(0xFFFFFFFFu, sum, off);

    __shared__ float wsum[8];
    int lane = threadIdx.x & 31;
    int wid  = threadIdx.x >> 5;
    if (lane == 0) wsum[wid] = sum;
    __syncthreads();
    if (wid == 0) {
        float s = (lane < 8) ? wsum[lane] : 0.f;
        #pragma unroll
        for (int off = 4; off > 0; off >>= 1)
            s += __shfl_down_sync(0xFFFFFFFFu, s, off);
        if (lane == 0) atomicAdd(&g_acc, s);
    }
}

// ---------------- Pass D: sigmoid + reset ----------------
__global__ void bm25_finalize(float* __restrict__ out) {
    float s = g_acc;
    g_acc = 0.f;                                  // restore invariant for next launch
    out[0] = 1.0f / (1.0f + __expf(-s));
}

// ---------------------------------------------------------------------------
extern "C" void kernel_launch(void* const* d_in, const int* in_sizes, int n_in,
                              void* d_out, int out_size) {
    const int*   ids = (const int*)d_in[0];       // [2, L] int32
    // d_in[1] = masks (unused by reference forward)
    const float* DF  = (const float*)d_in[2];     // [vocab] float32

    int twoL  = in_sizes[0];
    int L     = twoL >> 1;
    int vocab = in_sizes[2];

    float Ld = (float)L;
    // C1 = K1 * (1 - B + B * Ld / LAVE)
    float C1 = 1.2f * (1.0f - 0.75f + 0.75f * Ld / 56.0f);

    bm25_hist<<<2368, 256>>>((const int4*)ids, twoL >> 2, L >> 2, (unsigned)vocab);
    bm25_score<<<1024, 256>>>((const float4*)DF, vocab >> 2, C1);
    bm25_finalize<<<1, 1>>>((float*)d_out);
}